// round 16
// baseline (speedup 1.0000x reference)
#include <cuda_runtime.h>
#include <cuda_bf16.h>
#include <math.h>
#include <stdint.h>

// Problem constants
#define S    2048
#define HID  1024
#define NH   16
#define NKV  4
#define HD   64

// ---------------- fragment-ordered scratch (device globals) -----------------
__device__ uint32_t gXh[32 * 32 * 1024], gXl[32 * 32 * 1024];   // X A-frag
__device__ uint32_t gWh[12 * 32 * 2048], gWl[12 * 32 * 2048];   // Wq|Wk|Wv B-frag
__device__ uint32_t gWoh[8 * 32 * 2048], gWol[8 * 32 * 2048];   // Wo B-frag
__device__ uint32_t gQh[16 * 32 * 2048], gQl[16 * 32 * 2048];   // Q attn A-frag
__device__ uint32_t gKh[4 * 32 * 2048],  gKl[4 * 32 * 2048];    // K attn B-frag
__device__ uint32_t gVh[4 * 32 * 2048],  gVl[4 * 32 * 2048];    // V attn B-frag
__device__ uint32_t gAh[32 * 32 * 1024], gAl[32 * 32 * 1024];   // attn out A-frag

// ---------------- helpers ----------------------------------------------------
__device__ __forceinline__ void bsplit(float x, float y, uint32_t& hi, uint32_t& lo) {
    __nv_bfloat162 h = __floats2bfloat162_rn(x, y);
    float hx = __bfloat162float(h.x);
    float hy = __bfloat162float(h.y);
    __nv_bfloat162 l = __floats2bfloat162_rn(x - hx, y - hy);
    hi = *(uint32_t*)&h;
    lo = *(uint32_t*)&l;
}

__device__ __forceinline__ void mma16(float* d, const uint32_t* a, const uint32_t* b) {
    asm volatile(
        "mma.sync.aligned.m16n8k16.row.col.f32.bf16.bf16.f32 "
        "{%0,%1,%2,%3}, {%4,%5,%6,%7}, {%8,%9}, {%0,%1,%2,%3};"
        : "+f"(d[0]), "+f"(d[1]), "+f"(d[2]), "+f"(d[3])
        : "r"(a[0]), "r"(a[1]), "r"(a[2]), "r"(a[3]), "r"(b[0]), "r"(b[1]));
}

__device__ __forceinline__ void cp16(uint32_t saddr, const void* g) {
    asm volatile("cp.async.cg.shared.global [%0], [%1], 16;" :: "r"(saddr), "l"(g));
}
#define CP_COMMIT asm volatile("cp.async.commit_group;" ::: "memory")
#define CP_WAIT0  asm volatile("cp.async.wait_group 0;" ::: "memory")
#define CP_WAIT1  asm volatile("cp.async.wait_group 1;" ::: "memory")
#define CP_WAIT2  asm volatile("cp.async.wait_group 2;" ::: "memory")

#define L2T16 (13.287712379549449f / 16.0f)   // log2(10000)/16

// ================= merged gather-style conversion kernel =====================
__global__ __launch_bounds__(256) void convAll_kernel(
    const float* __restrict__ X,
    const float* __restrict__ Wq, const float* __restrict__ Wk,
    const float* __restrict__ Wv, const float* __restrict__ Wo)
{
    const int bx = blockIdx.x;
    const int tid = threadIdx.x;

    if (bx < 1024) {
        int t = bx * 256 + tid;
        int chunkg = t >> 8;
        int fr = t & 255;
        int ln = fr & 31, smt = fr >> 5;
        int s = smt >> 2, mt = smt & 3;
        int mb = chunkg >> 5, ch = chunkg & 31;
        int c = ln & 3, r8 = ln >> 2;
        int rowA = mb * 64 + mt * 16 + r8;
        int kb = ch * 32 + s * 16 + c * 2;

        float2 v0 = *(const float2*)(X + (size_t)rowA * HID + kb);
        float2 v1 = *(const float2*)(X + (size_t)(rowA + 8) * HID + kb);
        float2 v2 = *(const float2*)(X + (size_t)rowA * HID + kb + 8);
        float2 v3 = *(const float2*)(X + (size_t)(rowA + 8) * HID + kb + 8);
        uint4 H, L;
        bsplit(v0.x, v0.y, H.x, L.x);
        bsplit(v1.x, v1.y, H.y, L.y);
        bsplit(v2.x, v2.y, H.z, L.z);
        bsplit(v3.x, v3.y, H.w, L.w);
        *(uint4*)&gXh[((size_t)chunkg << 10) + fr * 4] = H;
        *(uint4*)&gXl[((size_t)chunkg << 10) + fr * 4] = L;
    } else {
        const float* W; uint32_t *Gh, *Gl; int N, nb_base, t;
        if (bx < 2048)      { W = Wq; N = 1024; nb_base = 0;  t = (bx - 1024) * 256 + tid;
                              Gh = gWh;  Gl = gWl; }
        else if (bx < 2304) { W = Wk; N = 256;  nb_base = 8;  t = (bx - 2048) * 256 + tid;
                              Gh = gWh;  Gl = gWl; }
        else if (bx < 2560) { W = Wv; N = 256;  nb_base = 10; t = (bx - 2304) * 256 + tid;
                              Gh = gWh;  Gl = gWl; }
        else                { W = Wo; N = 1024; nb_base = 0;  t = (bx - 2560) * 256 + tid;
                              Gh = gWoh; Gl = gWol; }
        int chunkg = t >> 10;
        int fr = t & 1023;
        int ln = fr & 31, snt = fr >> 5;
        int s = snt >> 4, nt = snt & 15;
        int nb = chunkg >> 5, ch = chunkg & 31;
        int c = ln & 3, nn7 = ln >> 2;
        int n = nb * 128 + nt * 8 + nn7;
        int k0 = ch * 32 + s * 16 + c * 2;
        int k1 = k0 + 8;

        float a0 = W[(size_t)k0 * N + n];
        float a1 = W[(size_t)(k0 + 1) * N + n];
        float b0 = W[(size_t)k1 * N + n];
        float b1 = W[(size_t)(k1 + 1) * N + n];
        uint2 H, L;
        bsplit(a0, a1, H.x, L.x);
        bsplit(b0, b1, H.y, L.y);
        size_t base = ((size_t)((nb_base + nb) * 32 + ch) << 11) + fr * 2;
        *(uint2*)&Gh[base] = H;
        *(uint2*)&Gl[base] = L;
    }
}

// ================= fragment GEMM (3xBF16, 3-stage, 1 barrier/chunk) ==========
#define GEMM_SMEM (3 * 6144 * 4)

__global__ __launch_bounds__(128, 3) void gemm_frag_kernel(
    const uint32_t* __restrict__ Agh, const uint32_t* __restrict__ Agl,
    const uint32_t* __restrict__ Wgh, const uint32_t* __restrict__ Wgl,
    float* __restrict__ Cout, int qkv)
{
    extern __shared__ uint32_t sm[];
    const uint32_t sb = (uint32_t)__cvta_generic_to_shared(sm);
    const int tid  = threadIdx.x;
    const int wid  = tid >> 5;
    const int lane = tid & 31;
    const int wm   = wid & 1;
    const int wn   = wid >> 1;
    const int mb   = blockIdx.y;
    const int bx   = blockIdx.x;
    const int m0   = mb * 64;

    const uint32_t* Ah_src = Agh + ((size_t)mb << 15);
    const uint32_t* Al_src = Agl + ((size_t)mb << 15);
    const uint32_t* Bh_src = Wgh + ((size_t)bx << 16);
    const uint32_t* Bl_src = Wgl + ((size_t)bx << 16);

    float acc[2][8][4];
    #pragma unroll
    for (int i = 0; i < 2; i++)
        #pragma unroll
        for (int j = 0; j < 8; j++)
            #pragma unroll
            for (int v = 0; v < 4; v++) acc[i][j][v] = 0.f;

    auto issue = [&](int ch, int buf) {
        uint32_t db = sb + buf * 6144 * 4;
        #pragma unroll
        for (int i = 0; i < 2; i++) {
            int j = tid + i * 128;
            cp16(db + j * 16,             Ah_src + (ch << 10) + j * 4);
            cp16(db + 4096 + j * 16,      Al_src + (ch << 10) + j * 4);
        }
        #pragma unroll
        for (int i = 0; i < 4; i++) {
            int j = tid + i * 128;
            cp16(db + 8192 + j * 16,      Bh_src + (ch << 11) + j * 4);
            cp16(db + 16384 + j * 16,     Bl_src + (ch << 11) + j * 4);
        }
    };
    auto compute = [&](int buf) {
        const uint32_t* Ah = sm + buf * 6144;
        const uint32_t* Al = Ah + 1024;
        const uint32_t* Bh = Ah + 2048;
        const uint32_t* Bl = Ah + 4096;
        #pragma unroll
        for (int s = 0; s < 2; s++) {
            uint32_t a_h[2][4], a_l[2][4];
            #pragma unroll
            for (int mt = 0; mt < 2; mt++) {
                *(uint4*)a_h[mt] = *(const uint4*)&Ah[((s * 4 + wm * 2 + mt) * 32 + lane) * 4];
                *(uint4*)a_l[mt] = *(const uint4*)&Al[((s * 4 + wm * 2 + mt) * 32 + lane) * 4];
            }
            #pragma unroll
            for (int ntb = 0; ntb < 2; ntb++) {
                uint32_t b_h[4][2], b_l[4][2];
                #pragma unroll
                for (int j = 0; j < 4; j++) {
                    int nt = wn * 8 + ntb * 4 + j;
                    *(uint2*)b_h[j] = *(const uint2*)&Bh[((s * 16 + nt) * 32 + lane) * 2];
                    *(uint2*)b_l[j] = *(const uint2*)&Bl[((s * 16 + nt) * 32 + lane) * 2];
                }
                #pragma unroll
                for (int j = 0; j < 4; j++)
                    #pragma unroll
                    for (int mt = 0; mt < 2; mt++)
                        mma16(acc[mt][ntb * 4 + j], a_h[mt], b_h[j]);
                #pragma unroll
                for (int j = 0; j < 4; j++)
                    #pragma unroll
                    for (int mt = 0; mt < 2; mt++)
                        mma16(acc[mt][ntb * 4 + j], a_h[mt], b_l[j]);
                #pragma unroll
                for (int j = 0; j < 4; j++)
                    #pragma unroll
                    for (int mt = 0; mt < 2; mt++)
                        mma16(acc[mt][ntb * 4 + j], a_l[mt], b_h[j]);
            }
        }
    };

    issue(0, 0); CP_COMMIT;
    issue(1, 1); CP_COMMIT;
    for (int ch = 0; ch < 32; ch++) {
        if (ch < 31) { CP_WAIT1; } else { CP_WAIT0; }
        __syncthreads();
        compute(ch % 3);
        if (ch + 2 < 32) { issue(ch + 2, (ch + 2) % 3); CP_COMMIT; }
    }

    // ---- epilogue ----
    const int mode = qkv ? (bx < 8 ? 1 : (bx < 10 ? 2 : 3)) : 0;

    #pragma unroll
    for (int mt = 0; mt < 2; mt++) {
        const int tile16 = wm * 2 + mt;
        const int row = m0 + tile16 * 16 + (lane >> 2);
        #pragma unroll
        for (int nt = 0; nt < 8; nt++) {
            const int nglob = wn * 8 + nt;
            const int nn = nglob & 7;
            float v0 = acc[mt][nt][0], v1 = acc[mt][nt][1];
            float v2 = acc[mt][nt][2], v3 = acc[mt][nt][3];

            if (mode == 0) {
                int col = bx * 128 + nglob * 8 + (lane & 3) * 2;
                *(float2*)(Cout + (size_t)row * HID + col) = make_float2(v0, v1);
                *(float2*)(Cout + (size_t)(row + 8) * HID + col) = make_float2(v2, v3);
            } else if (mode == 1) {          // Q: RoPE + 1/8 -> attn A-frag
                int h2 = bx * 2 + (nglob >> 3);
                int fidx = (nn * 4 + (lane & 3)) & 15;
                float inv = exp2f(-(float)fidx * L2T16);
                uint32_t base = ((uint32_t)(h2 * 32 + mb) << 11)
                              + ((tile16 * 4 + (nn >> 1)) * 32 + lane) * 4
                              + ((nn & 1) << 1);
                float sn, cs;
                sincosf((float)row * inv, &sn, &cs);
                uint32_t hh, ll;
                bsplit((v0 * cs - v1 * sn) * 0.125f, (v0 * sn + v1 * cs) * 0.125f, hh, ll);
                gQh[base] = hh; gQl[base] = ll;
                sincosf((float)(row + 8) * inv, &sn, &cs);
                bsplit((v2 * cs - v3 * sn) * 0.125f, (v2 * sn + v3 * cs) * 0.125f, hh, ll);
                gQh[base + 1] = hh; gQl[base + 1] = ll;
            } else if (mode == 2) {          // K: RoPE -> attn B-frag
                int kvh2 = (bx - 8) * 2 + (nglob >> 3);
                int fidx = (nn * 4 + (lane & 3)) & 15;
                float inv = exp2f(-(float)fidx * L2T16);
                uint32_t kb = (uint32_t)(kvh2 * 32 + mb) << 11;
                int sK = nn >> 1;
                int kt8 = tile16 * 2;
                float sn, cs;
                sincosf((float)row * inv, &sn, &cs);
                uint32_t hh, ll;
                bsplit(v0 * cs - v1 * sn, v0 * sn + v1 * cs, hh, ll);
                uint32_t i0 = kb + (((sK * 8 + kt8) * 32 + lane) << 1) + (nn & 1);
                gKh[i0] = hh; gKl[i0] = ll;
                sincosf((float)(row + 8) * inv, &sn, &cs);
                bsplit(v2 * cs - v3 * sn, v2 * sn + v3 * cs, hh, ll);
                uint32_t i1 = kb + (((sK * 8 + kt8 + 1) * 32 + lane) << 1) + (nn & 1);
                gKh[i1] = hh; gKl[i1] = ll;
            } else {                         // V: pair rows via shfl -> attn B-frag
                int kvh2 = (bx - 10) * 2 + (nglob >> 3);
                float b0 = __shfl_xor_sync(0xffffffffu, v0, 4);
                float b1 = __shfl_xor_sync(0xffffffffu, v1, 4);
                float b2 = __shfl_xor_sync(0xffffffffu, v2, 4);
                float b3 = __shfl_xor_sync(0xffffffffu, v3, 4);
                if (!(lane & 4)) {
                    uint32_t vb = (uint32_t)(kvh2 * 32 + mb) << 11;
                    #pragma unroll
                    for (int grp = 0; grp < 2; grp++) {
                        int kp = tile16 * 8 + grp * 4 + (lane >> 3);
                        int sv = kp >> 3, cv = kp & 3, rgv = (kp >> 2) & 1;
                        #pragma unroll
                        for (int colsel = 0; colsel < 2; colsel++) {
                            float x0 = grp ? (colsel ? v3 : v2) : (colsel ? v1 : v0);
                            float x1 = grp ? (colsel ? b3 : b2) : (colsel ? b1 : b0);
                            int d7 = (lane & 3) * 2 + colsel;
                            uint32_t idx = vb + ((((sv * 8 + nn) << 5)
                                         + ((d7 << 2) | cv)) << 1) + rgv;
                            uint32_t hh, ll;
                            bsplit(x0, x1, hh, ll);
                            gVh[idx] = hh; gVl[idx] = ll;
                        }
                    }
                }
            }
        }
    }
}

// ================= MMA flash attention (bf16 3x, causal, GQA 4:1) ============
// 48 KB smem: K double-buffered (2x16KB), V single-buffered (16KB).
// ql not register-resident (re-loaded from L2 per tile) -> fits 128 regs,
// 4 CTAs/SM.  V(t) cp.async issued at tile start, consumed after softmax.
#define ATT_SMEM (12288 * 4)

__global__ __launch_bounds__(128, 4) void attn_frag_kernel()
{
    extern __shared__ uint32_t sm[];
    const uint32_t sb = (uint32_t)__cvta_generic_to_shared(sm);
    const int tid  = threadIdx.x;
    const int wid  = tid >> 5;
    const int lane = tid & 31;

    const int h   = blockIdx.y;
    const int qt  = gridDim.x - 1 - blockIdx.x;   // heavy tiles first
    const int q0  = qt * 64;
    const int kvh = h >> 2;

    const uint32_t* Qbh = gQh + ((size_t)(h * 32 + qt) << 11);
    const uint32_t* Qbl = gQl + ((size_t)(h * 32 + qt) << 11);

    uint32_t qh[4][4];
    #pragma unroll
    for (int s = 0; s < 4; s++)
        *(uint4*)qh[s] = *(const uint4*)&Qbh[((wid * 4 + s) * 32 + lane) * 4];

    const int r0 = q0 + wid * 16 + (lane >> 2);
    const int r1 = r0 + 8;
    const int c2 = (lane & 3) * 2;

    float m0 = -1e30f, m1 = -1e30f, l0 = 0.f, l1 = 0.f;
    float o[8][4];
    #pragma unroll
    for (int nt = 0; nt < 8; nt++)
        #pragma unroll
        for (int v = 0; v < 4; v++) o[nt][v] = 0.f;

    auto issueK = [&](int t, int b) {
        uint32_t db = sb + b * 4096 * 4;
        const uint32_t* kh = gKh + ((size_t)(kvh * 32 + t) << 11);
        const uint32_t* kl = gKl + ((size_t)(kvh * 32 + t) << 11);
        #pragma unroll
        for (int i = 0; i < 4; i++) {
            int j = tid + i * 128;
            cp16(db + j * 16,         kh + j * 4);
            cp16(db + 8192 + j * 16,  kl + j * 4);
        }
    };
    auto issueV = [&](int t) {
        uint32_t db = sb + 8192 * 4;
        const uint32_t* vh = gVh + ((size_t)(kvh * 32 + t) << 11);
        const uint32_t* vl = gVl + ((size_t)(kvh * 32 + t) << 11);
        #pragma unroll
        for (int i = 0; i < 4; i++) {
            int j = tid + i * 128;
            cp16(db + j * 16,         vh + j * 4);
            cp16(db + 8192 + j * 16,  vl + j * 4);
        }
    };

    issueK(0, 0); CP_COMMIT;
    for (int t = 0; t <= qt; t++) {
        const int b = t & 1;
        // vbuf free: t==0 trivially, else end-of-iter barrier guarantees.
        issueV(t); CP_COMMIT;
        if (t < qt) { issueK(t + 1, 1 - b); CP_COMMIT; }
        // K(t) arrived: up to {V(t), K(t+1)} may remain pending.
        if (t < qt) { CP_WAIT2; } else { CP_WAIT1; }
        __syncthreads();                 // K(t) visible to all warps

        const uint32_t* Kh = sm + b * 4096;
        const uint32_t* Kl = Kh + 2048;
        const int kv0 = t * 64;

        // ---- per-tile ql reload (keeps registers <= 128) ----
        uint32_t ql[4][4];
        #pragma unroll
        for (int s = 0; s < 4; s++)
            *(uint4*)ql[s] = *(const uint4*)&Qbl[((wid * 4 + s) * 32 + lane) * 4];

        // ---- S = Q K^T (3xBF16) ----
        float s_[8][4];
        #pragma unroll
        for (int nt = 0; nt < 8; nt++)
            #pragma unroll
            for (int v = 0; v < 4; v++) s_[nt][v] = 0.f;
        #pragma unroll
        for (int s = 0; s < 4; s++) {
            #pragma unroll
            for (int ntb = 0; ntb < 2; ntb++) {
                uint32_t k_h[4][2], k_l[4][2];
                #pragma unroll
                for (int j = 0; j < 4; j++) {
                    int nt = ntb * 4 + j;
                    *(uint2*)k_h[j] = *(const uint2*)&Kh[((s * 8 + nt) * 32 + lane) * 2];
                    *(uint2*)k_l[j] = *(const uint2*)&Kl[((s * 8 + nt) * 32 + lane) * 2];
                }
                #pragma unroll
                for (int j = 0; j < 4; j++) mma16(s_[ntb * 4 + j], qh[s], k_h[j]);
                #pragma unroll
                for (int j = 0; j < 4; j++) mma16(s_[ntb * 4 + j], qh[s], k_l[j]);
                #pragma unroll
                for (int j = 0; j < 4; j++) mma16(s_[ntb * 4 + j], ql[s], k_h[j]);
            }
        }

        if (t == qt) {
            #pragma unroll
            for (int nt = 0; nt < 8; nt++) {
                int cb = kv0 + nt * 8 + c2;
                if (cb > r0)     s_[nt][0] = -1e30f;
                if (cb + 1 > r0) s_[nt][1] = -1e30f;
                if (cb > r1)     s_[nt][2] = -1e30f;
                if (cb + 1 > r1) s_[nt][3] = -1e30f;
            }
        }

        // ---- online softmax ----
        float tm0 = -1e30f, tm1 = -1e30f;
        #pragma unroll
        for (int nt = 0; nt < 8; nt++) {
            tm0 = fmaxf(tm0, fmaxf(s_[nt][0], s_[nt][1]));
            tm1 = fmaxf(tm1, fmaxf(s_[nt][2], s_[nt][3]));
        }
        tm0 = fmaxf(tm0, __shfl_xor_sync(0xffffffffu, tm0, 1));
        tm0 = fmaxf(tm0, __shfl_xor_sync(0xffffffffu, tm0, 2));
        tm1 = fmaxf(tm1, __shfl_xor_sync(0xffffffffu, tm1, 1));
        tm1 = fmaxf(tm1, __shfl_xor_sync(0xffffffffu, tm1, 2));
        float mn0 = fmaxf(m0, tm0), mn1 = fmaxf(m1, tm1);
        float f0 = __expf(m0 - mn0), f1 = __expf(m1 - mn1);
        m0 = mn0; m1 = mn1;
        float rs0 = 0.f, rs1 = 0.f;
        #pragma unroll
        for (int nt = 0; nt < 8; nt++) {
            s_[nt][0] = __expf(s_[nt][0] - mn0); rs0 += s_[nt][0];
            s_[nt][1] = __expf(s_[nt][1] - mn0); rs0 += s_[nt][1];
            s_[nt][2] = __expf(s_[nt][2] - mn1); rs1 += s_[nt][2];
            s_[nt][3] = __expf(s_[nt][3] - mn1); rs1 += s_[nt][3];
        }
        rs0 += __shfl_xor_sync(0xffffffffu, rs0, 1);
        rs0 += __shfl_xor_sync(0xffffffffu, rs0, 2);
        rs1 += __shfl_xor_sync(0xffffffffu, rs1, 1);
        rs1 += __shfl_xor_sync(0xffffffffu, rs1, 2);
        l0 = l0 * f0 + rs0;
        l1 = l1 * f1 + rs1;
        #pragma unroll
        for (int nt = 0; nt < 8; nt++) {
            o[nt][0] *= f0; o[nt][1] *= f0;
            o[nt][2] *= f1; o[nt][3] *= f1;
        }

        // V(t) arrived (K(t+1) may remain pending), then make visible.
        if (t < qt) { CP_WAIT1; } else { CP_WAIT0; }
        __syncthreads();

        const uint32_t* Vh = sm + 8192;
        const uint32_t* Vl = Vh + 2048;

        // ---- O += P V ----
        #pragma unroll
        for (int s = 0; s < 4; s++) {
            uint32_t ph[4], pl[4];
            bsplit(s_[2 * s][0],     s_[2 * s][1],     ph[0], pl[0]);
            bsplit(s_[2 * s][2],     s_[2 * s][3],     ph[1], pl[1]);
            bsplit(s_[2 * s + 1][0], s_[2 * s + 1][1], ph[2], pl[2]);
            bsplit(s_[2 * s + 1][2], s_[2 * s + 1][3], ph[3], pl[3]);
            #pragma unroll
            for (int ntb = 0; ntb < 2; ntb++) {
                uint32_t v_h[4][2], v_l[4][2];
                #pragma unroll
                for (int j = 0; j < 4; j++) {
                    int nt = ntb * 4 + j;
                    *(uint2*)v_h[j] = *(const uint2*)&Vh[((s * 8 + nt) * 32 + lane) * 2];
                    *(uint2*)v_l[j] = *(const uint2*)&Vl[((s * 8 + nt) * 32 + lane) * 2];
                }
                #pragma unroll
                for (int j = 0; j < 4; j++) mma16(o[ntb * 4 + j], ph, v_h[j]);
                #pragma unroll
                for (int j = 0; j < 4; j++) mma16(o[ntb * 4 + j], ph, v_l[j]);
                #pragma unroll
                for (int j = 0; j < 4; j++) mma16(o[ntb * 4 + j], pl, v_h[j]);
            }
        }
        __syncthreads();   // all warps done with vbuf -> next issueV may overwrite
    }

    // ---- epilogue: write A-fragment hi/lo for the out-projection ----
    float il0 = 1.0f / l0, il1 = 1.0f / l1;
    #pragma unroll
    for (int nt = 0; nt < 8; nt++) {
        int chA = h * 2 + (nt >> 2);
        int sA  = (nt & 3) >> 1;
        uint32_t base = ((uint32_t)(qt * 32 + chA) << 10)
                      + ((sA * 4 + wid) * 32 + lane) * 4 + ((nt & 1) << 1);
        uint32_t hh, ll;
        bsplit(o[nt][0] * il0, o[nt][1] * il0, hh, ll);
        gAh[base] = hh; gAl[base] = ll;
        bsplit(o[nt][2] * il1, o[nt][3] * il1, hh, ll);
        gAh[base + 1] = hh; gAl[base + 1] = ll;
    }
}

// ---------------- launch ----------------------------------------------------
extern "C" void kernel_launch(void* const* d_in, const int* in_sizes, int n_in,
                              void* d_out, int out_size)
{
    const float* X  = (const float*)d_in[0];
    const float* Wq = (const float*)d_in[1];
    const float* Wk = (const float*)d_in[2];
    const float* Wv = (const float*)d_in[3];
    const float* Wo = (const float*)d_in[4];
    float* out = (float*)d_out;

    uint32_t *pXh, *pXl, *pWh, *pWl, *pWoh, *pWol, *pAh, *pAl;
    cudaGetSymbolAddress((void**)&pXh, gXh);
    cudaGetSymbolAddress((void**)&pXl, gXl);
    cudaGetSymbolAddress((void**)&pWh, gWh);
    cudaGetSymbolAddress((void**)&pWl, gWl);
    cudaGetSymbolAddress((void**)&pWoh, gWoh);
    cudaGetSymbolAddress((void**)&pWol, gWol);
    cudaGetSymbolAddress((void**)&pAh, gAh);
    cudaGetSymbolAddress((void**)&pAl, gAl);

    cudaFuncSetAttribute(gemm_frag_kernel,
                         cudaFuncAttributeMaxDynamicSharedMemorySize, GEMM_SMEM);
    cudaFuncSetAttribute(attn_frag_kernel,
                         cudaFuncAttributeMaxDynamicSharedMemorySize, ATT_SMEM);

    // Merged gather-style conversions (coalesced stores)
    convAll_kernel<<<3584, 256>>>(X, Wq, Wk, Wv, Wo);

    // Merged QKV (modes: bx<8 Q+RoPE, bx 8-9 K+RoPE, bx 10-11 V)
    gemm_frag_kernel<<<dim3(12, 32), 128, GEMM_SMEM>>>(pXh, pXl, pWh, pWl, nullptr, 1);

    // Flash attention (reads/writes fragment-ordered globals)
    attn_frag_kernel<<<dim3(32, NH), 128, ATT_SMEM>>>();

    // Output projection (mode 0: plain fp32 store)
    gemm_frag_kernel<<<dim3(8, 32), 128, GEMM_SMEM>>>(pAh, pAl, pWoh, pWol, out, 0);
}

// round 17
// speedup vs baseline: 1.2111x; 1.2111x over previous
#include <cuda_runtime.h>
#include <cuda_bf16.h>
#include <cuda_fp16.h>
#include <math.h>
#include <stdint.h>

// Problem constants
#define S    2048
#define HID  1024
#define NH   16
#define NKV  4
#define HD   64

// ---------------- fragment-ordered scratch (device globals) -----------------
__device__ uint32_t gXh[32 * 32 * 1024], gXl[32 * 32 * 1024];   // X A-frag (bf16)
__device__ uint32_t gWh[12 * 32 * 2048], gWl[12 * 32 * 2048];   // Wq|Wk|Wv B-frag (bf16)
__device__ uint32_t gWoh[8 * 32 * 2048], gWol[8 * 32 * 2048];   // Wo B-frag (bf16)
__device__ uint32_t gQh[16 * 32 * 2048], gQl[16 * 32 * 2048];   // Q attn A-frag (bf16)
__device__ uint32_t gKh[4 * 32 * 2048],  gKl[4 * 32 * 2048];    // K attn B-frag (bf16)
__device__ uint32_t gVh[4 * 32 * 2048],  gVl[4 * 32 * 2048];    // V attn B-frag (FP16 hi/lo)
__device__ uint32_t gAh[32 * 32 * 1024], gAl[32 * 32 * 1024];   // attn out A-frag (bf16)

// ---------------- helpers ----------------------------------------------------
__device__ __forceinline__ void bsplit(float x, float y, uint32_t& hi, uint32_t& lo) {
    __nv_bfloat162 h = __floats2bfloat162_rn(x, y);
    float hx = __bfloat162float(h.x);
    float hy = __bfloat162float(h.y);
    __nv_bfloat162 l = __floats2bfloat162_rn(x - hx, y - hy);
    hi = *(uint32_t*)&h;
    lo = *(uint32_t*)&l;
}

// fp16 hi/lo split (10 mantissa bits; hi+lo ~ 2^-21 accurate)
__device__ __forceinline__ void fsplit(float x, float y, uint32_t& hi, uint32_t& lo) {
    __half2 h = __floats2half2_rn(x, y);
    float hx = __half2float(__low2half(h));
    float hy = __half2float(__high2half(h));
    __half2 l = __floats2half2_rn(x - hx, y - hy);
    hi = *(uint32_t*)&h;
    lo = *(uint32_t*)&l;
}
__device__ __forceinline__ uint32_t fpack(float x, float y) {
    __half2 h = __floats2half2_rn(x, y);
    return *(uint32_t*)&h;
}

// m16n8k16 bf16 mma, D += A*B
__device__ __forceinline__ void mma16(float* d, const uint32_t* a, const uint32_t* b) {
    asm volatile(
        "mma.sync.aligned.m16n8k16.row.col.f32.bf16.bf16.f32 "
        "{%0,%1,%2,%3}, {%4,%5,%6,%7}, {%8,%9}, {%0,%1,%2,%3};"
        : "+f"(d[0]), "+f"(d[1]), "+f"(d[2]), "+f"(d[3])
        : "r"(a[0]), "r"(a[1]), "r"(a[2]), "r"(a[3]), "r"(b[0]), "r"(b[1]));
}
// m16n8k16 fp16 mma, D += A*B
__device__ __forceinline__ void mma16h(float* d, const uint32_t* a, const uint32_t* b) {
    asm volatile(
        "mma.sync.aligned.m16n8k16.row.col.f32.f16.f16.f32 "
        "{%0,%1,%2,%3}, {%4,%5,%6,%7}, {%8,%9}, {%0,%1,%2,%3};"
        : "+f"(d[0]), "+f"(d[1]), "+f"(d[2]), "+f"(d[3])
        : "r"(a[0]), "r"(a[1]), "r"(a[2]), "r"(a[3]), "r"(b[0]), "r"(b[1]));
}

__device__ __forceinline__ void cp16(uint32_t saddr, const void* g) {
    asm volatile("cp.async.cg.shared.global [%0], [%1], 16;" :: "r"(saddr), "l"(g));
}
#define CP_COMMIT asm volatile("cp.async.commit_group;" ::: "memory")
#define CP_WAIT0  asm volatile("cp.async.wait_group 0;" ::: "memory")
#define CP_WAIT1  asm volatile("cp.async.wait_group 1;" ::: "memory")

#define L2T16 (13.287712379549449f / 16.0f)   // log2(10000)/16

// ================= merged gather-style conversion kernel =====================
__global__ __launch_bounds__(256) void convAll_kernel(
    const float* __restrict__ X,
    const float* __restrict__ Wq, const float* __restrict__ Wk,
    const float* __restrict__ Wv, const float* __restrict__ Wo)
{
    const int bx = blockIdx.x;
    const int tid = threadIdx.x;

    if (bx < 1024) {
        int t = bx * 256 + tid;
        int chunkg = t >> 8;
        int fr = t & 255;
        int ln = fr & 31, smt = fr >> 5;
        int s = smt >> 2, mt = smt & 3;
        int mb = chunkg >> 5, ch = chunkg & 31;
        int c = ln & 3, r8 = ln >> 2;
        int rowA = mb * 64 + mt * 16 + r8;
        int kb = ch * 32 + s * 16 + c * 2;

        float2 v0 = *(const float2*)(X + (size_t)rowA * HID + kb);
        float2 v1 = *(const float2*)(X + (size_t)(rowA + 8) * HID + kb);
        float2 v2 = *(const float2*)(X + (size_t)rowA * HID + kb + 8);
        float2 v3 = *(const float2*)(X + (size_t)(rowA + 8) * HID + kb + 8);
        uint4 H, L;
        bsplit(v0.x, v0.y, H.x, L.x);
        bsplit(v1.x, v1.y, H.y, L.y);
        bsplit(v2.x, v2.y, H.z, L.z);
        bsplit(v3.x, v3.y, H.w, L.w);
        *(uint4*)&gXh[((size_t)chunkg << 10) + fr * 4] = H;
        *(uint4*)&gXl[((size_t)chunkg << 10) + fr * 4] = L;
    } else {
        const float* W; uint32_t *Gh, *Gl; int N, nb_base, t;
        if (bx < 2048)      { W = Wq; N = 1024; nb_base = 0;  t = (bx - 1024) * 256 + tid;
                              Gh = gWh;  Gl = gWl; }
        else if (bx < 2304) { W = Wk; N = 256;  nb_base = 8;  t = (bx - 2048) * 256 + tid;
                              Gh = gWh;  Gl = gWl; }
        else if (bx < 2560) { W = Wv; N = 256;  nb_base = 10; t = (bx - 2304) * 256 + tid;
                              Gh = gWh;  Gl = gWl; }
        else                { W = Wo; N = 1024; nb_base = 0;  t = (bx - 2560) * 256 + tid;
                              Gh = gWoh; Gl = gWol; }
        int chunkg = t >> 10;
        int fr = t & 1023;
        int ln = fr & 31, snt = fr >> 5;
        int s = snt >> 4, nt = snt & 15;
        int nb = chunkg >> 5, ch = chunkg & 31;
        int c = ln & 3, nn7 = ln >> 2;
        int n = nb * 128 + nt * 8 + nn7;
        int k0 = ch * 32 + s * 16 + c * 2;
        int k1 = k0 + 8;

        float a0 = W[(size_t)k0 * N + n];
        float a1 = W[(size_t)(k0 + 1) * N + n];
        float b0 = W[(size_t)k1 * N + n];
        float b1 = W[(size_t)(k1 + 1) * N + n];
        uint2 H, L;
        bsplit(a0, a1, H.x, L.x);
        bsplit(b0, b1, H.y, L.y);
        size_t base = ((size_t)((nb_base + nb) * 32 + ch) << 11) + fr * 2;
        *(uint2*)&Gh[base] = H;
        *(uint2*)&Gl[base] = L;
    }
}

// ================= fragment GEMM (3xBF16, 3-stage, 1 barrier/chunk) ==========
#define GEMM_SMEM (3 * 6144 * 4)

__global__ __launch_bounds__(128, 3) void gemm_frag_kernel(
    const uint32_t* __restrict__ Agh, const uint32_t* __restrict__ Agl,
    const uint32_t* __restrict__ Wgh, const uint32_t* __restrict__ Wgl,
    float* __restrict__ Cout, int qkv)
{
    extern __shared__ uint32_t sm[];
    const uint32_t sb = (uint32_t)__cvta_generic_to_shared(sm);
    const int tid  = threadIdx.x;
    const int wid  = tid >> 5;
    const int lane = tid & 31;
    const int wm   = wid & 1;
    const int wn   = wid >> 1;
    const int mb   = blockIdx.y;
    const int bx   = blockIdx.x;
    const int m0   = mb * 64;

    const uint32_t* Ah_src = Agh + ((size_t)mb << 15);
    const uint32_t* Al_src = Agl + ((size_t)mb << 15);
    const uint32_t* Bh_src = Wgh + ((size_t)bx << 16);
    const uint32_t* Bl_src = Wgl + ((size_t)bx << 16);

    float acc[2][8][4];
    #pragma unroll
    for (int i = 0; i < 2; i++)
        #pragma unroll
        for (int j = 0; j < 8; j++)
            #pragma unroll
            for (int v = 0; v < 4; v++) acc[i][j][v] = 0.f;

    auto issue = [&](int ch, int buf) {
        uint32_t db = sb + buf * 6144 * 4;
        #pragma unroll
        for (int i = 0; i < 2; i++) {
            int j = tid + i * 128;
            cp16(db + j * 16,             Ah_src + (ch << 10) + j * 4);
            cp16(db + 4096 + j * 16,      Al_src + (ch << 10) + j * 4);
        }
        #pragma unroll
        for (int i = 0; i < 4; i++) {
            int j = tid + i * 128;
            cp16(db + 8192 + j * 16,      Bh_src + (ch << 11) + j * 4);
            cp16(db + 16384 + j * 16,     Bl_src + (ch << 11) + j * 4);
        }
    };
    auto compute = [&](int buf) {
        const uint32_t* Ah = sm + buf * 6144;
        const uint32_t* Al = Ah + 1024;
        const uint32_t* Bh = Ah + 2048;
        const uint32_t* Bl = Ah + 4096;
        #pragma unroll
        for (int s = 0; s < 2; s++) {
            uint32_t a_h[2][4], a_l[2][4];
            #pragma unroll
            for (int mt = 0; mt < 2; mt++) {
                *(uint4*)a_h[mt] = *(const uint4*)&Ah[((s * 4 + wm * 2 + mt) * 32 + lane) * 4];
                *(uint4*)a_l[mt] = *(const uint4*)&Al[((s * 4 + wm * 2 + mt) * 32 + lane) * 4];
            }
            #pragma unroll
            for (int ntb = 0; ntb < 2; ntb++) {
                uint32_t b_h[4][2], b_l[4][2];
                #pragma unroll
                for (int j = 0; j < 4; j++) {
                    int nt = wn * 8 + ntb * 4 + j;
                    *(uint2*)b_h[j] = *(const uint2*)&Bh[((s * 16 + nt) * 32 + lane) * 2];
                    *(uint2*)b_l[j] = *(const uint2*)&Bl[((s * 16 + nt) * 32 + lane) * 2];
                }
                #pragma unroll
                for (int j = 0; j < 4; j++)
                    #pragma unroll
                    for (int mt = 0; mt < 2; mt++)
                        mma16(acc[mt][ntb * 4 + j], a_h[mt], b_h[j]);
                #pragma unroll
                for (int j = 0; j < 4; j++)
                    #pragma unroll
                    for (int mt = 0; mt < 2; mt++)
                        mma16(acc[mt][ntb * 4 + j], a_h[mt], b_l[j]);
                #pragma unroll
                for (int j = 0; j < 4; j++)
                    #pragma unroll
                    for (int mt = 0; mt < 2; mt++)
                        mma16(acc[mt][ntb * 4 + j], a_l[mt], b_h[j]);
            }
        }
    };

    issue(0, 0); CP_COMMIT;
    issue(1, 1); CP_COMMIT;
    for (int ch = 0; ch < 32; ch++) {
        if (ch < 31) { CP_WAIT1; } else { CP_WAIT0; }
        __syncthreads();
        compute(ch % 3);
        if (ch + 2 < 32) { issue(ch + 2, (ch + 2) % 3); CP_COMMIT; }
    }

    // ---- epilogue ----
    const int mode = qkv ? (bx < 8 ? 1 : (bx < 10 ? 2 : 3)) : 0;

    #pragma unroll
    for (int mt = 0; mt < 2; mt++) {
        const int tile16 = wm * 2 + mt;
        const int row = m0 + tile16 * 16 + (lane >> 2);
        #pragma unroll
        for (int nt = 0; nt < 8; nt++) {
            const int nglob = wn * 8 + nt;
            const int nn = nglob & 7;
            float v0 = acc[mt][nt][0], v1 = acc[mt][nt][1];
            float v2 = acc[mt][nt][2], v3 = acc[mt][nt][3];

            if (mode == 0) {
                int col = bx * 128 + nglob * 8 + (lane & 3) * 2;
                *(float2*)(Cout + (size_t)row * HID + col) = make_float2(v0, v1);
                *(float2*)(Cout + (size_t)(row + 8) * HID + col) = make_float2(v2, v3);
            } else if (mode == 1) {          // Q: RoPE + 1/8 -> attn A-frag (bf16)
                int h2 = bx * 2 + (nglob >> 3);
                int fidx = (nn * 4 + (lane & 3)) & 15;
                float inv = exp2f(-(float)fidx * L2T16);
                uint32_t base = ((uint32_t)(h2 * 32 + mb) << 11)
                              + ((tile16 * 4 + (nn >> 1)) * 32 + lane) * 4
                              + ((nn & 1) << 1);
                float sn, cs;
                sincosf((float)row * inv, &sn, &cs);
                uint32_t hh, ll;
                bsplit((v0 * cs - v1 * sn) * 0.125f, (v0 * sn + v1 * cs) * 0.125f, hh, ll);
                gQh[base] = hh; gQl[base] = ll;
                sincosf((float)(row + 8) * inv, &sn, &cs);
                bsplit((v2 * cs - v3 * sn) * 0.125f, (v2 * sn + v3 * cs) * 0.125f, hh, ll);
                gQh[base + 1] = hh; gQl[base + 1] = ll;
            } else if (mode == 2) {          // K: RoPE -> attn B-frag (bf16)
                int kvh2 = (bx - 8) * 2 + (nglob >> 3);
                int fidx = (nn * 4 + (lane & 3)) & 15;
                float inv = exp2f(-(float)fidx * L2T16);
                uint32_t kb = (uint32_t)(kvh2 * 32 + mb) << 11;
                int sK = nn >> 1;
                int kt8 = tile16 * 2;
                float sn, cs;
                sincosf((float)row * inv, &sn, &cs);
                uint32_t hh, ll;
                bsplit(v0 * cs - v1 * sn, v0 * sn + v1 * cs, hh, ll);
                uint32_t i0 = kb + (((sK * 8 + kt8) * 32 + lane) << 1) + (nn & 1);
                gKh[i0] = hh; gKl[i0] = ll;
                sincosf((float)(row + 8) * inv, &sn, &cs);
                bsplit(v2 * cs - v3 * sn, v2 * sn + v3 * cs, hh, ll);
                uint32_t i1 = kb + (((sK * 8 + kt8 + 1) * 32 + lane) << 1) + (nn & 1);
                gKh[i1] = hh; gKl[i1] = ll;
            } else {                         // V: pair rows via shfl -> attn B-frag (FP16 hi/lo)
                int kvh2 = (bx - 10) * 2 + (nglob >> 3);
                float b0 = __shfl_xor_sync(0xffffffffu, v0, 4);
                float b1 = __shfl_xor_sync(0xffffffffu, v1, 4);
                float b2 = __shfl_xor_sync(0xffffffffu, v2, 4);
                float b3 = __shfl_xor_sync(0xffffffffu, v3, 4);
                if (!(lane & 4)) {
                    uint32_t vb = (uint32_t)(kvh2 * 32 + mb) << 11;
                    #pragma unroll
                    for (int grp = 0; grp < 2; grp++) {
                        int kp = tile16 * 8 + grp * 4 + (lane >> 3);
                        int sv = kp >> 3, cv = kp & 3, rgv = (kp >> 2) & 1;
                        #pragma unroll
                        for (int colsel = 0; colsel < 2; colsel++) {
                            float x0 = grp ? (colsel ? v3 : v2) : (colsel ? v1 : v0);
                            float x1 = grp ? (colsel ? b3 : b2) : (colsel ? b1 : b0);
                            int d7 = (lane & 3) * 2 + colsel;
                            uint32_t idx = vb + ((((sv * 8 + nn) << 5)
                                         + ((d7 << 2) | cv)) << 1) + rgv;
                            uint32_t hh, ll;
                            fsplit(x0, x1, hh, ll);
                            gVh[idx] = hh; gVl[idx] = ll;
                        }
                    }
                }
            }
        }
    }
}

// ================= MMA flash attention =======================================
// QK: 3-pass bf16 (unchanged).  PV: 2-pass fp16 (P packed to fp16 hi only;
// V stored fp16 hi/lo -> dropped term = (P - fp16(P))*V ~ 2^-11, the same
// truncation regime that measured rel_err 3.6e-4 in R5).
// 2 smem buffers, single barrier per KV tile (R13 config).
#define ATT_SMEM (2 * 8192 * 4)

__global__ __launch_bounds__(128, 3) void attn_frag_kernel()
{
    extern __shared__ uint32_t sm[];
    const uint32_t sb = (uint32_t)__cvta_generic_to_shared(sm);
    const int tid  = threadIdx.x;
    const int wid  = tid >> 5;
    const int lane = tid & 31;

    const int h   = blockIdx.y;
    const int qt  = gridDim.x - 1 - blockIdx.x;   // heavy tiles first
    const int q0  = qt * 64;
    const int kvh = h >> 2;

    uint32_t qh[4][4], ql[4][4];
    {
        const uint32_t* Qb = gQh + ((size_t)(h * 32 + qt) << 11);
        const uint32_t* Qb2 = gQl + ((size_t)(h * 32 + qt) << 11);
        #pragma unroll
        for (int s = 0; s < 4; s++) {
            *(uint4*)qh[s] = *(const uint4*)&Qb[((wid * 4 + s) * 32 + lane) * 4];
            *(uint4*)ql[s] = *(const uint4*)&Qb2[((wid * 4 + s) * 32 + lane) * 4];
        }
    }

    const int r0 = q0 + wid * 16 + (lane >> 2);
    const int r1 = r0 + 8;
    const int c2 = (lane & 3) * 2;

    float m0 = -1e30f, m1 = -1e30f, l0 = 0.f, l1 = 0.f;
    float o[8][4];
    #pragma unroll
    for (int nt = 0; nt < 8; nt++)
        #pragma unroll
        for (int v = 0; v < 4; v++) o[nt][v] = 0.f;

    auto issue = [&](int t, int buf) {
        uint32_t db = sb + buf * 8192 * 4;
        const uint32_t* kh = gKh + ((size_t)(kvh * 32 + t) << 11);
        const uint32_t* kl = gKl + ((size_t)(kvh * 32 + t) << 11);
        const uint32_t* vh = gVh + ((size_t)(kvh * 32 + t) << 11);
        const uint32_t* vl = gVl + ((size_t)(kvh * 32 + t) << 11);
        #pragma unroll
        for (int i = 0; i < 4; i++) {
            int j = tid + i * 128;
            cp16(db + j * 16,          kh + j * 4);
            cp16(db + 8192 + j * 16,   kl + j * 4);
            cp16(db + 16384 + j * 16,  vh + j * 4);
            cp16(db + 24576 + j * 16,  vl + j * 4);
        }
    };

    issue(0, 0); CP_COMMIT;
    for (int t = 0; t <= qt; t++) {
        CP_WAIT0;
        __syncthreads();
        if (t < qt) { issue(t + 1, (t + 1) & 1); CP_COMMIT; }

        const uint32_t* Kh = sm + (t & 1) * 8192;
        const uint32_t* Kl = Kh + 2048;
        const uint32_t* Vh = Kh + 4096;
        const uint32_t* Vl = Kh + 6144;
        const int kv0 = t * 64;

        float s_[8][4];
        #pragma unroll
        for (int nt = 0; nt < 8; nt++)
            #pragma unroll
            for (int v = 0; v < 4; v++) s_[nt][v] = 0.f;
        #pragma unroll
        for (int s = 0; s < 4; s++) {
            #pragma unroll
            for (int ntb = 0; ntb < 2; ntb++) {
                uint32_t k_h[4][2], k_l[4][2];
                #pragma unroll
                for (int j = 0; j < 4; j++) {
                    int nt = ntb * 4 + j;
                    *(uint2*)k_h[j] = *(const uint2*)&Kh[((s * 8 + nt) * 32 + lane) * 2];
                    *(uint2*)k_l[j] = *(const uint2*)&Kl[((s * 8 + nt) * 32 + lane) * 2];
                }
                #pragma unroll
                for (int j = 0; j < 4; j++) mma16(s_[ntb * 4 + j], qh[s], k_h[j]);
                #pragma unroll
                for (int j = 0; j < 4; j++) mma16(s_[ntb * 4 + j], qh[s], k_l[j]);
                #pragma unroll
                for (int j = 0; j < 4; j++) mma16(s_[ntb * 4 + j], ql[s], k_h[j]);
            }
        }

        if (t == qt) {
            #pragma unroll
            for (int nt = 0; nt < 8; nt++) {
                int cb = kv0 + nt * 8 + c2;
                if (cb > r0)     s_[nt][0] = -1e30f;
                if (cb + 1 > r0) s_[nt][1] = -1e30f;
                if (cb > r1)     s_[nt][2] = -1e30f;
                if (cb + 1 > r1) s_[nt][3] = -1e30f;
            }
        }

        float tm0 = -1e30f, tm1 = -1e30f;
        #pragma unroll
        for (int nt = 0; nt < 8; nt++) {
            tm0 = fmaxf(tm0, fmaxf(s_[nt][0], s_[nt][1]));
            tm1 = fmaxf(tm1, fmaxf(s_[nt][2], s_[nt][3]));
        }
        tm0 = fmaxf(tm0, __shfl_xor_sync(0xffffffffu, tm0, 1));
        tm0 = fmaxf(tm0, __shfl_xor_sync(0xffffffffu, tm0, 2));
        tm1 = fmaxf(tm1, __shfl_xor_sync(0xffffffffu, tm1, 1));
        tm1 = fmaxf(tm1, __shfl_xor_sync(0xffffffffu, tm1, 2));
        float mn0 = fmaxf(m0, tm0), mn1 = fmaxf(m1, tm1);
        float f0 = __expf(m0 - mn0), f1 = __expf(m1 - mn1);
        m0 = mn0; m1 = mn1;
        float rs0 = 0.f, rs1 = 0.f;
        #pragma unroll
        for (int nt = 0; nt < 8; nt++) {
            s_[nt][0] = __expf(s_[nt][0] - mn0); rs0 += s_[nt][0];
            s_[nt][1] = __expf(s_[nt][1] - mn0); rs0 += s_[nt][1];
            s_[nt][2] = __expf(s_[nt][2] - mn1); rs1 += s_[nt][2];
            s_[nt][3] = __expf(s_[nt][3] - mn1); rs1 += s_[nt][3];
        }
        rs0 += __shfl_xor_sync(0xffffffffu, rs0, 1);
        rs0 += __shfl_xor_sync(0xffffffffu, rs0, 2);
        rs1 += __shfl_xor_sync(0xffffffffu, rs1, 1);
        rs1 += __shfl_xor_sync(0xffffffffu, rs1, 2);
        l0 = l0 * f0 + rs0;
        l1 = l1 * f1 + rs1;
        #pragma unroll
        for (int nt = 0; nt < 8; nt++) {
            o[nt][0] *= f0; o[nt][1] *= f0;
            o[nt][2] *= f1; o[nt][3] *= f1;
        }

        // ---- O += P V : 2-pass fp16 (P hi only; V hi + V lo) ----
        #pragma unroll
        for (int s = 0; s < 4; s++) {
            uint32_t ph[4];
            ph[0] = fpack(s_[2 * s][0],     s_[2 * s][1]);
            ph[1] = fpack(s_[2 * s][2],     s_[2 * s][3]);
            ph[2] = fpack(s_[2 * s + 1][0], s_[2 * s + 1][1]);
            ph[3] = fpack(s_[2 * s + 1][2], s_[2 * s + 1][3]);
            #pragma unroll
            for (int ntb = 0; ntb < 2; ntb++) {
                uint32_t v_h[4][2], v_l[4][2];
                #pragma unroll
                for (int j = 0; j < 4; j++) {
                    int nt = ntb * 4 + j;
                    *(uint2*)v_h[j] = *(const uint2*)&Vh[((s * 8 + nt) * 32 + lane) * 2];
                    *(uint2*)v_l[j] = *(const uint2*)&Vl[((s * 8 + nt) * 32 + lane) * 2];
                }
                #pragma unroll
                for (int j = 0; j < 4; j++) mma16h(o[ntb * 4 + j], ph, v_h[j]);
                #pragma unroll
                for (int j = 0; j < 4; j++) mma16h(o[ntb * 4 + j], ph, v_l[j]);
            }
        }
    }

    // ---- epilogue: write A-fragment hi/lo for the out-projection ----
    float il0 = 1.0f / l0, il1 = 1.0f / l1;
    #pragma unroll
    for (int nt = 0; nt < 8; nt++) {
        int chA = h * 2 + (nt >> 2);
        int sA  = (nt & 3) >> 1;
        uint32_t base = ((uint32_t)(qt * 32 + chA) << 10)
                      + ((sA * 4 + wid) * 32 + lane) * 4 + ((nt & 1) << 1);
        uint32_t hh, ll;
        bsplit(o[nt][0] * il0, o[nt][1] * il0, hh, ll);
        gAh[base] = hh; gAl[base] = ll;
        bsplit(o[nt][2] * il1, o[nt][3] * il1, hh, ll);
        gAh[base + 1] = hh; gAl[base + 1] = ll;
    }
}

// ---------------- launch ----------------------------------------------------
extern "C" void kernel_launch(void* const* d_in, const int* in_sizes, int n_in,
                              void* d_out, int out_size)
{
    const float* X  = (const float*)d_in[0];
    const float* Wq = (const float*)d_in[1];
    const float* Wk = (const float*)d_in[2];
    const float* Wv = (const float*)d_in[3];
    const float* Wo = (const float*)d_in[4];
    float* out = (float*)d_out;

    uint32_t *pXh, *pXl, *pWh, *pWl, *pWoh, *pWol, *pAh, *pAl;
    cudaGetSymbolAddress((void**)&pXh, gXh);
    cudaGetSymbolAddress((void**)&pXl, gXl);
    cudaGetSymbolAddress((void**)&pWh, gWh);
    cudaGetSymbolAddress((void**)&pWl, gWl);
    cudaGetSymbolAddress((void**)&pWoh, gWoh);
    cudaGetSymbolAddress((void**)&pWol, gWol);
    cudaGetSymbolAddress((void**)&pAh, gAh);
    cudaGetSymbolAddress((void**)&pAl, gAl);

    cudaFuncSetAttribute(gemm_frag_kernel,
                         cudaFuncAttributeMaxDynamicSharedMemorySize, GEMM_SMEM);
    cudaFuncSetAttribute(attn_frag_kernel,
                         cudaFuncAttributeMaxDynamicSharedMemorySize, ATT_SMEM);

    // Merged gather-style conversions (coalesced stores)
    convAll_kernel<<<3584, 256>>>(X, Wq, Wk, Wv, Wo);

    // Merged QKV (modes: bx<8 Q+RoPE, bx 8-9 K+RoPE, bx 10-11 V->fp16)
    gemm_frag_kernel<<<dim3(12, 32), 128, GEMM_SMEM>>>(pXh, pXl, pWh, pWl, nullptr, 1);

    // Flash attention (QK 3-pass bf16, PV 2-pass fp16)
    attn_frag_kernel<<<dim3(32, NH), 128, ATT_SMEM>>>();

    // Output projection (mode 0: plain fp32 store)
    gemm_frag_kernel<<<dim3(8, 32), 128, GEMM_SMEM>>>(pAh, pAl, pWoh, pWol, out, 0);
}